// round 2
// baseline (speedup 1.0000x reference)
#include <cuda_runtime.h>
#include <cstdint>

// TT embedding lookup:
//   P = (216,216,216), Q = (2,4,2), R = (128,128), tables = 2, batch = 1024
//   out[t,b, q0*8+q1*2+q2] = sum_{r0,r1} A[q0,r0] * Bm[r0, q1*128+r1] * C[r1,q2]
// where A = core0[t, i0] ([2,128]), Bm = core1[t, i1] ([128,512]), C = core2[t, i2] ([128,2]).
//
// One CTA of 128 threads per (table, sample). Thread t owns Bm columns
// 4t..4t+3 (warp w <-> q1 = w). Block streams the 256KB Bm slice with
// coalesced LDG.128 (2KB per row per iteration), accumulating
// S[q0][j] = sum_r0 A[q0,r0]*Bm[r0, 4t+j] in registers, then contracts with
// per-thread C values and warp-reduces over the 32 r1-groups.
//
// NOTE: lS_i is int32 on the wire (JAX silently downgrades int64 without x64).

#define P0 216
#define P1 216
#define P2 216
#define TABLES 2

__global__ __launch_bounds__(128, 8) void tt_lookup_kernel(
    const int* __restrict__ lS_i,         // [TABLES, B] int32
    const float* __restrict__ core0,      // [TABLES, P0, 256]
    const float* __restrict__ core1,      // [TABLES, P1, 65536]
    const float* __restrict__ core2,      // [TABLES, P2, 256]
    float* __restrict__ out,              // [TABLES, B, 16]
    int batch)
{
    const int sample = blockIdx.x;              // 0 .. TABLES*batch-1
    const int table  = sample / batch;
    const int t      = threadIdx.x;             // 0..127
    const int lane   = t & 31;
    const int w      = t >> 5;                  // warp id == q1

    // index decomposition (values < 216^3 fit in 32-bit)
    const int id  = lS_i[sample];
    const int i0  = id / (P1 * P2);
    const int rem = id - i0 * (P1 * P2);
    const int i1  = rem / P2;
    const int i2  = rem - i1 * P2;

    const float* a  = core0 + ((size_t)table * P0 + i0) * 256;     // [q0*128 + r0]
    const float* bm = core1 + ((size_t)table * P1 + i1) * 65536;   // [r0*512 + col]
    const float* c  = core2 + ((size_t)table * P2 + i2) * 256;     // [r1*2 + q2]

    // A into smem, transposed to [r0] -> (A0, A1) for broadcast reads
    __shared__ float2 sA[128];
    {
        float a0 = a[t];
        float a1 = a[t + 128];
        sA[t] = make_float2(a0, a1);
    }

    // Per-thread C values: r1 = 4*lane + j  (same for every warp).
    // c layout: C[r1][q2]; 8 consecutive floats starting at 8*lane.
    const float4 c01 = *reinterpret_cast<const float4*>(c + 8 * lane);     // C[4l+0], C[4l+1]
    const float4 c23 = *reinterpret_cast<const float4*>(c + 8 * lane + 4); // C[4l+2], C[4l+3]

    __syncthreads();

    // Mainloop: S[q0][j] = sum_r0 A[q0,r0] * Bm[r0, 4t+j]
    float s00 = 0.f, s01 = 0.f, s02 = 0.f, s03 = 0.f;
    float s10 = 0.f, s11 = 0.f, s12 = 0.f, s13 = 0.f;
    const float* bp = bm + 4 * t;

    #pragma unroll 8
    for (int r0 = 0; r0 < 128; ++r0) {
        const float4 v = *reinterpret_cast<const float4*>(bp + (size_t)r0 * 512);
        const float2 av = sA[r0];
        s00 = fmaf(av.x, v.x, s00);
        s01 = fmaf(av.x, v.y, s01);
        s02 = fmaf(av.x, v.z, s02);
        s03 = fmaf(av.x, v.w, s03);
        s10 = fmaf(av.y, v.x, s10);
        s11 = fmaf(av.y, v.y, s11);
        s12 = fmaf(av.y, v.z, s12);
        s13 = fmaf(av.y, v.w, s13);
    }

    // Epilogue: contract with C over this thread's 4 r1 values.
    // o[q0][q2] partial for q1 = w.
    float o00 = s00 * c01.x + s01 * c01.z + s02 * c23.x + s03 * c23.z;
    float o01 = s00 * c01.y + s01 * c01.w + s02 * c23.y + s03 * c23.w;
    float o10 = s10 * c01.x + s11 * c01.z + s12 * c23.x + s13 * c23.z;
    float o11 = s10 * c01.y + s11 * c01.w + s12 * c23.y + s13 * c23.w;

    // Warp reduction over the 32 r1-groups (each warp owns one q1).
    #pragma unroll
    for (int off = 16; off; off >>= 1) {
        o00 += __shfl_down_sync(0xffffffffu, o00, off);
        o01 += __shfl_down_sync(0xffffffffu, o01, off);
        o10 += __shfl_down_sync(0xffffffffu, o10, off);
        o11 += __shfl_down_sync(0xffffffffu, o11, off);
    }

    if (lane == 0) {
        float* op = out + (size_t)sample * 16 + w * 2;
        op[0] = o00;   // q0=0, q1=w, q2=0
        op[1] = o01;   // q0=0, q1=w, q2=1
        op[8] = o10;   // q0=1, q1=w, q2=0
        op[9] = o11;   // q0=1, q1=w, q2=1
    }
}

extern "C" void kernel_launch(void* const* d_in, const int* in_sizes, int n_in,
                              void* d_out, int out_size) {
    const int*   lS_i  = (const int*)d_in[0];
    const float* core0 = (const float*)d_in[1];
    const float* core1 = (const float*)d_in[2];
    const float* core2 = (const float*)d_in[3];
    float*       out   = (float*)d_out;

    const int n_samples = in_sizes[0];          // TABLES * batch = 2048
    const int batch     = n_samples / TABLES;

    tt_lookup_kernel<<<n_samples, 128>>>(lS_i, core0, core1, core2, out, batch);
}